// round 10
// baseline (speedup 1.0000x reference)
#include <cuda_runtime.h>
#include <cuda_bf16.h>
#include <cstdint>

#define B_   2
#define S_   2048
#define D_   1024
#define H_   16
#define DK_  64
#define EPS_ 0.1f
#define M_ROWS (B_ * S_)          // 4096
#define N_QKV  (3 * D_)           // 3072

// Scratch (allocation-free requirement -> __device__ globals)
__device__ __nv_bfloat16 g_qkvh[M_ROWS * N_QKV];
__device__ __nv_bfloat16 g_qkvl[M_ROWS * N_QKV];
__device__ __nv_bfloat16 g_ah[M_ROWS * D_];
__device__ __nv_bfloat16 g_al[M_ROWS * D_];
__device__ __nv_bfloat16 g_wqh[N_QKV * D_];
__device__ __nv_bfloat16 g_wql[N_QKV * D_];
__device__ __nv_bfloat16 g_woh[D_ * D_];
__device__ __nv_bfloat16 g_wol[D_ * D_];

// ---------------------------------------------------------------------------
// helpers
// ---------------------------------------------------------------------------
__device__ __forceinline__ uint32_t smem_u32(const void* p) {
    return (uint32_t)__cvta_generic_to_shared(p);
}
__device__ __forceinline__ void ldsm_x4(uint32_t& r0, uint32_t& r1, uint32_t& r2,
                                        uint32_t& r3, uint32_t addr) {
    asm volatile("ldmatrix.sync.aligned.m8n8.x4.shared.b16 {%0,%1,%2,%3}, [%4];"
                 : "=r"(r0), "=r"(r1), "=r"(r2), "=r"(r3) : "r"(addr));
}
__device__ __forceinline__ void ldsm_x2(uint32_t& r0, uint32_t& r1, uint32_t addr) {
    asm volatile("ldmatrix.sync.aligned.m8n8.x2.shared.b16 {%0,%1}, [%2];"
                 : "=r"(r0), "=r"(r1) : "r"(addr));
}
__device__ __forceinline__ void ldsm_x2_t(uint32_t& r0, uint32_t& r1, uint32_t addr) {
    asm volatile("ldmatrix.sync.aligned.m8n8.x2.trans.shared.b16 {%0,%1}, [%2];"
                 : "=r"(r0), "=r"(r1) : "r"(addr));
}
__device__ __forceinline__ void mma16816(float c[4], const uint32_t a[4],
                                         const uint32_t b[2]) {
    asm volatile(
        "mma.sync.aligned.m16n8k16.row.col.f32.bf16.bf16.f32 "
        "{%0,%1,%2,%3}, {%4,%5,%6,%7}, {%8,%9}, {%0,%1,%2,%3};"
        : "+f"(c[0]), "+f"(c[1]), "+f"(c[2]), "+f"(c[3])
        : "r"(a[0]), "r"(a[1]), "r"(a[2]), "r"(a[3]), "r"(b[0]), "r"(b[1]));
}
__device__ __forceinline__ uint32_t pack_hi2(float x, float y) {
    __nv_bfloat162 t = __floats2bfloat162_rn(x, y);
    return *(uint32_t*)&t;
}
__device__ __forceinline__ uint32_t pack_lo2(float x, float y) {
    float hx = __bfloat162float(__float2bfloat16(x));
    float hy = __bfloat162float(__float2bfloat16(y));
    __nv_bfloat162 t = __floats2bfloat162_rn(x - hx, y - hy);
    return *(uint32_t*)&t;
}
__device__ __forceinline__ void cpasync16(uint32_t saddr, const void* g) {
    asm volatile("cp.async.ca.shared.global [%0], [%1], 16;" :: "r"(saddr), "l"(g));
}
__device__ __forceinline__ void cpcommit() {
    asm volatile("cp.async.commit_group;");
}
template <int N>
__device__ __forceinline__ void cpwait() {
    asm volatile("cp.async.wait_group %0;" :: "n"(N));
}

// ---------------------------------------------------------------------------
// fp32 -> (hi,lo) bf16 split
// ---------------------------------------------------------------------------
__global__ void split_kernel(const float* __restrict__ in,
                             __nv_bfloat16* __restrict__ hi,
                             __nv_bfloat16* __restrict__ lo, int n4) {
    int i = blockIdx.x * blockDim.x + threadIdx.x;
    if (i >= n4) return;
    float4 f = ((const float4*)in)[i];
    uint2 hh, ll;
    hh.x = pack_hi2(f.x, f.y); hh.y = pack_hi2(f.z, f.w);
    ll.x = pack_lo2(f.x, f.y); ll.y = pack_lo2(f.z, f.w);
    ((uint2*)hi)[i] = hh;
    ((uint2*)lo)[i] = ll;
}

// ---------------------------------------------------------------------------
// guard clamp
// ---------------------------------------------------------------------------
__device__ __forceinline__ float guard_clamp(
    float v, int m, int n,
    const float* __restrict__ akmin, const float* __restrict__ akmax,
    const float* __restrict__ avmin, const float* __restrict__ avmax) {
    const int c = n >> 10;
    const int b  = m >> 11;
    const int h  = (n & 1023) >> 6;
    const int ch = n & 63;
    const int ai = ((b << 4) + h) * 64 + ch;
    const float amin = (c == 1) ? akmin[ai] : avmin[ai];
    const float amax = (c == 1) ? akmax[ai] : avmax[ai];
    float lo = fmaxf(v - EPS_, amin);
    float hi = fminf(v + EPS_, amax);
    lo = fminf(lo, hi);
    return fmaxf(lo, fminf(v, hi));
}

// ---------------------------------------------------------------------------
// Split-bf16 tensor-core GEMM:  C[M,N] = A[M,K] @ B[N,K]^T + bias
// Block tile 128x256, 8 warps (2 M x 4 N), warp tile 64x64.
// BK=16, 4-stage cp.async ring (3 in flight).
// Stage layout (BYTES): Ah@0 (6144) | Al@6144 | Bh@12288 (12288) | Bl@24576.
// MODE 1: QKV epilogue (q-scale / kv-clamp, split-bf16 out).  MODE 0: fp32 out.
// ---------------------------------------------------------------------------
#define GSTG    36864            // bytes per stage
#define OFF_AL  6144             // bytes
#define OFF_BH  12288            // bytes
#define OFF_BL  24576            // bytes
#define GEMM_SMEM (4 * GSTG)     // 147456 bytes

template <int MODE>
__global__ __launch_bounds__(256) void gemm_bf16s_kernel(
    const __nv_bfloat16* __restrict__ Ah, const __nv_bfloat16* __restrict__ Al,
    const __nv_bfloat16* __restrict__ Bh, const __nv_bfloat16* __restrict__ Bl,
    const float* __restrict__ bias,
    float* __restrict__ C,
    __nv_bfloat16* __restrict__ Ch, __nv_bfloat16* __restrict__ Cl,
    int M, int N, int K,
    const float* __restrict__ akmin, const float* __restrict__ akmax,
    const float* __restrict__ avmin, const float* __restrict__ avmax)
{
    extern __shared__ __nv_bfloat16 smem[];

    const int tid  = threadIdx.x;
    const int wid  = tid >> 5;
    const int lane = tid & 31;
    const int warp_m = (wid & 1) * 64;
    const int warp_n = (wid >> 1) * 64;
    const int bm = blockIdx.y * 128;
    const int bn = blockIdx.x * 256;

    const int KS = K >> 4;     // 64

    const int la_r = tid >> 1, la_c = (tid & 1) * 8;
    const uint32_t sb0 = smem_u32(smem);

    auto load_stage = [&](int ks, int buf) {
        const uint32_t sb = sb0 + buf * GSTG;          // byte base of stage
        const int k0 = ks * 16;
        // A: 128 rows x 2 chunks of 8 bf16
        {
            const uint32_t sa = sb + (la_r * 24 + la_c) * 2;
            const size_t go = (size_t)(bm + la_r) * K + k0 + la_c;
            cpasync16(sa, Ah + go);
            cpasync16(sa + OFF_AL, Al + go);
        }
        // B: 256 rows x 2 chunks of 8 bf16
#pragma unroll
        for (int i = 0; i < 2; i++) {
            const int chk = tid + i * 256;
            const int r = chk >> 1, c = (chk & 1) * 8;
            const uint32_t sa = sb + OFF_BH + (r * 24 + c) * 2;
            const size_t go = (size_t)(bn + r) * K + k0 + c;
            cpasync16(sa, Bh + go);
            cpasync16(sa + (OFF_BL - OFF_BH), Bl + go);
        }
        cpcommit();
    };

    float c[4][8][4];
#pragma unroll
    for (int mt = 0; mt < 4; mt++)
#pragma unroll
        for (int nt = 0; nt < 8; nt++)
#pragma unroll
            for (int e = 0; e < 4; e++) c[mt][nt][e] = 0.0f;

    load_stage(0, 0);
    load_stage(1, 1);
    load_stage(2, 2);

    // fragment lane mappings
    const int ar = lane & 15, ac = (lane >> 4) << 3;        // A x4
    const int bprow = (lane & 7) + ((lane >> 4) << 3);      // B x4 row-in-pair
    const int bpcol = ((lane >> 3) & 1) << 3;               // B x4 k-col

    for (int ks = 0; ks < KS; ks++) {
        const int buf = ks & 3;
        cpwait<2>();
        __syncthreads();
        const uint32_t sb = sb0 + buf * GSTG;

        // B fragments: 4 x4-loads cover 8 n-groups (hi and lo)
        uint32_t bfh[8][2], bfl[8][2];
#pragma unroll
        for (int p = 0; p < 4; p++) {
            const uint32_t off = ((warp_n + p * 16 + bprow) * 24 + bpcol) * 2;
            ldsm_x4(bfh[2 * p][0], bfh[2 * p][1], bfh[2 * p + 1][0], bfh[2 * p + 1][1],
                    sb + OFF_BH + off);
            ldsm_x4(bfl[2 * p][0], bfl[2 * p][1], bfl[2 * p + 1][0], bfl[2 * p + 1][1],
                    sb + OFF_BL + off);
        }
#pragma unroll
        for (int mt = 0; mt < 4; mt++) {
            uint32_t afh[4], afl[4];
            const uint32_t aoff = ((warp_m + mt * 16 + ar) * 24 + ac) * 2;
            ldsm_x4(afh[0], afh[1], afh[2], afh[3], sb + aoff);
            ldsm_x4(afl[0], afl[1], afl[2], afl[3], sb + OFF_AL + aoff);
#pragma unroll
            for (int nt = 0; nt < 8; nt++) {
                mma16816(c[mt][nt], afh, bfh[nt]);
                mma16816(c[mt][nt], afh, bfl[nt]);
                mma16816(c[mt][nt], afl, bfh[nt]);
            }
        }
        __syncthreads();
        // keep commit-count advancing even in the tail so cpwait<2> always
        // implies "stage ks complete"
        if (ks + 3 < KS) load_stage(ks + 3, (ks + 3) & 3);
        else cpcommit();
    }

    // Epilogue
    const int g = lane >> 2, t = lane & 3;
#pragma unroll
    for (int mt = 0; mt < 4; mt++) {
#pragma unroll
        for (int nt = 0; nt < 8; nt++) {
            const int n0 = bn + warp_n + nt * 8 + t * 2;
            const float b0 = bias[n0], b1 = bias[n0 + 1];
#pragma unroll
            for (int half = 0; half < 2; half++) {
                const int m = bm + warp_m + mt * 16 + g + half * 8;
                float v0 = c[mt][nt][half * 2 + 0] + b0;
                float v1 = c[mt][nt][half * 2 + 1] + b1;
                if (MODE == 1) {
                    if ((n0 >> 10) == 0) { v0 *= 0.125f; v1 *= 0.125f; }
                    else {
                        v0 = guard_clamp(v0, m, n0,     akmin, akmax, avmin, avmax);
                        v1 = guard_clamp(v1, m, n0 + 1, akmin, akmax, avmin, avmax);
                    }
                    *(uint32_t*)&Ch[(size_t)m * N + n0] = pack_hi2(v0, v1);
                    *(uint32_t*)&Cl[(size_t)m * N + n0] = pack_lo2(v0, v1);
                } else {
                    *(float2*)&C[(size_t)m * N + n0] = make_float2(v0, v1);
                }
            }
        }
    }
}

// ---------------------------------------------------------------------------
// Tensor-core flash attention over pre-split bf16 QKV (round-5, unchanged)
// ---------------------------------------------------------------------------
#define STR_ 72

__global__ __launch_bounds__(128) void attn_tc_kernel(
    const __nv_bfloat16* __restrict__ qkvh,
    const __nv_bfloat16* __restrict__ qkvl,
    __nv_bfloat16* __restrict__ oh, __nv_bfloat16* __restrict__ ol)
{
    extern __shared__ __nv_bfloat16 sb[];
    __nv_bfloat16* sQh = sb;
    __nv_bfloat16* sQl = sQh + 64 * STR_;
    __nv_bfloat16* sKh = sQl + 64 * STR_;
    __nv_bfloat16* sKl = sKh + 64 * STR_;
    __nv_bfloat16* sVh = sKl + 64 * STR_;
    __nv_bfloat16* sVl = sVh + 64 * STR_;

    const int qt = blockIdx.x, h = blockIdx.y, b = blockIdx.z;
    const int tid = threadIdx.x, w = tid >> 5, lane = tid & 31;
    const int g = lane >> 2, t = lane & 3;

#pragma unroll
    for (int it = 0; it < 4; it++) {
        const int idx = tid + it * 128;
        const int r = idx >> 3, c8 = (idx & 7) << 3;
        const size_t gb = ((size_t)(b * S_ + qt * 64 + r) * 3) * 1024 + h * 64 + c8;
        *(uint4*)&sQh[r * STR_ + c8] = *(const uint4*)(qkvh + gb);
        *(uint4*)&sQl[r * STR_ + c8] = *(const uint4*)(qkvl + gb);
    }
    __syncthreads();

    uint32_t aqh[4][4], aql[4][4];
    const int ar = lane & 15, ac8 = (lane >> 4) << 3;
#pragma unroll
    for (int k = 0; k < 4; k++) {
        const int roff = (w * 16 + ar) * STR_ + ac8 + k * 16;
        ldsm_x4(aqh[k][0], aqh[k][1], aqh[k][2], aqh[k][3], smem_u32(&sQh[roff]));
        ldsm_x4(aql[k][0], aql[k][1], aql[k][2], aql[k][3], smem_u32(&sQl[roff]));
    }

    float o[8][4];
#pragma unroll
    for (int dt = 0; dt < 8; dt++)
#pragma unroll
        for (int e = 0; e < 4; e++) o[dt][e] = 0.0f;
    float m0 = -1e30f, m1 = -1e30f, l0 = 0.0f, l1 = 0.0f;

    const int kr = lane & 7, kc = ((lane >> 3) & 1) << 3;
    const int vr = lane & 15;

    for (int kt = 0; kt < S_ / 64; kt++) {
        __syncthreads();
#pragma unroll
        for (int it = 0; it < 4; it++) {
            const int idx = tid + it * 128;
            const int r = idx >> 3, c8 = (idx & 7) << 3;
            const size_t gb =
                ((size_t)(b * S_ + kt * 64 + r) * 3) * 1024 + h * 64 + c8;
            *(uint4*)&sKh[r * STR_ + c8] = *(const uint4*)(qkvh + gb + 1024);
            *(uint4*)&sKl[r * STR_ + c8] = *(const uint4*)(qkvl + gb + 1024);
            *(uint4*)&sVh[r * STR_ + c8] = *(const uint4*)(qkvh + gb + 2048);
            *(uint4*)&sVl[r * STR_ + c8] = *(const uint4*)(qkvl + gb + 2048);
        }
        __syncthreads();

        float sc[8][4];
#pragma unroll
        for (int nt = 0; nt < 8; nt++)
#pragma unroll
            for (int e = 0; e < 4; e++) sc[nt][e] = 0.0f;
#pragma unroll
        for (int k = 0; k < 4; k++) {
#pragma unroll
            for (int nt = 0; nt < 8; nt++) {
                uint32_t bh[2], bl[2];
                const int boff = (nt * 8 + kr) * STR_ + kc + k * 16;
                ldsm_x2(bh[0], bh[1], smem_u32(&sKh[boff]));
                ldsm_x2(bl[0], bl[1], smem_u32(&sKl[boff]));
                mma16816(sc[nt], aqh[k], bh);
                mma16816(sc[nt], aqh[k], bl);
                mma16816(sc[nt], aql[k], bh);
            }
        }

        float mx0 = -1e30f, mx1 = -1e30f;
#pragma unroll
        for (int nt = 0; nt < 8; nt++) {
            mx0 = fmaxf(mx0, fmaxf(sc[nt][0], sc[nt][1]));
            mx1 = fmaxf(mx1, fmaxf(sc[nt][2], sc[nt][3]));
        }
        mx0 = fmaxf(mx0, __shfl_xor_sync(0xffffffffu, mx0, 1));
        mx0 = fmaxf(mx0, __shfl_xor_sync(0xffffffffu, mx0, 2));
        mx1 = fmaxf(mx1, __shfl_xor_sync(0xffffffffu, mx1, 1));
        mx1 = fmaxf(mx1, __shfl_xor_sync(0xffffffffu, mx1, 2));
        const float mn0 = fmaxf(m0, mx0), mn1 = fmaxf(m1, mx1);
        const float c0 = __expf(m0 - mn0), c1 = __expf(m1 - mn1);
        float rs0 = 0.0f, rs1 = 0.0f;
#pragma unroll
        for (int nt = 0; nt < 8; nt++) {
            sc[nt][0] = __expf(sc[nt][0] - mn0);
            sc[nt][1] = __expf(sc[nt][1] - mn0);
            sc[nt][2] = __expf(sc[nt][2] - mn1);
            sc[nt][3] = __expf(sc[nt][3] - mn1);
            rs0 += sc[nt][0] + sc[nt][1];
            rs1 += sc[nt][2] + sc[nt][3];
        }
        rs0 += __shfl_xor_sync(0xffffffffu, rs0, 1);
        rs0 += __shfl_xor_sync(0xffffffffu, rs0, 2);
        rs1 += __shfl_xor_sync(0xffffffffu, rs1, 1);
        rs1 += __shfl_xor_sync(0xffffffffu, rs1, 2);
        l0 = l0 * c0 + rs0;
        l1 = l1 * c1 + rs1;
        m0 = mn0; m1 = mn1;
#pragma unroll
        for (int dt = 0; dt < 8; dt++) {
            o[dt][0] *= c0; o[dt][1] *= c0;
            o[dt][2] *= c1; o[dt][3] *= c1;
        }

#pragma unroll
        for (int kq = 0; kq < 4; kq++) {
            uint32_t ph[4], pl[4];
            ph[0] = pack_hi2(sc[2 * kq][0], sc[2 * kq][1]);
            ph[1] = pack_hi2(sc[2 * kq][2], sc[2 * kq][3]);
            ph[2] = pack_hi2(sc[2 * kq + 1][0], sc[2 * kq + 1][1]);
            ph[3] = pack_hi2(sc[2 * kq + 1][2], sc[2 * kq + 1][3]);
            pl[0] = pack_lo2(sc[2 * kq][0], sc[2 * kq][1]);
            pl[1] = pack_lo2(sc[2 * kq][2], sc[2 * kq][3]);
            pl[2] = pack_lo2(sc[2 * kq + 1][0], sc[2 * kq + 1][1]);
            pl[3] = pack_lo2(sc[2 * kq + 1][2], sc[2 * kq + 1][3]);
#pragma unroll
            for (int dt = 0; dt < 8; dt++) {
                uint32_t bvh[2], bvl[2];
                const int voff = (kq * 16 + vr) * STR_ + dt * 8;
                ldsm_x2_t(bvh[0], bvh[1], smem_u32(&sVh[voff]));
                ldsm_x2_t(bvl[0], bvl[1], smem_u32(&sVl[voff]));
                mma16816(o[dt], ph, bvh);
                mma16816(o[dt], ph, bvl);
                mma16816(o[dt], pl, bvh);
            }
        }
    }

    const float inv0 = 1.0f / l0, inv1 = 1.0f / l1;
    const int r0 = qt * 64 + w * 16 + g;
    const int r1 = r0 + 8;
#pragma unroll
    for (int dt = 0; dt < 8; dt++) {
        const int d0 = h * 64 + dt * 8 + t * 2;
        const float x0 = o[dt][0] * inv0, x1 = o[dt][1] * inv0;
        const float y0 = o[dt][2] * inv1, y1 = o[dt][3] * inv1;
        const size_t p0 = (size_t)(b * S_ + r0) * 1024 + d0;
        const size_t p1 = (size_t)(b * S_ + r1) * 1024 + d0;
        *(uint32_t*)&oh[p0] = pack_hi2(x0, x1);
        *(uint32_t*)&ol[p0] = pack_lo2(x0, x1);
        *(uint32_t*)&oh[p1] = pack_hi2(y0, y1);
        *(uint32_t*)&ol[p1] = pack_lo2(y0, y1);
    }
}

// ---------------------------------------------------------------------------
extern "C" void kernel_launch(void* const* d_in, const int* in_sizes, int n_in,
                              void* d_out, int out_size)
{
    const float* x      = (const float*)d_in[0];
    const float* qkv_w  = (const float*)d_in[1];
    const float* qkv_b  = (const float*)d_in[2];
    const float* out_w  = (const float*)d_in[3];
    const float* out_b  = (const float*)d_in[4];
    const float* akmin  = (const float*)d_in[5];
    const float* akmax  = (const float*)d_in[6];
    const float* avmin  = (const float*)d_in[7];
    const float* avmax  = (const float*)d_in[8];
    float* out = (float*)d_out;

    __nv_bfloat16 *qkvh, *qkvl, *ah, *al, *wqh, *wql, *woh, *wol;
    cudaGetSymbolAddress((void**)&qkvh, g_qkvh);
    cudaGetSymbolAddress((void**)&qkvl, g_qkvl);
    cudaGetSymbolAddress((void**)&ah,  g_ah);
    cudaGetSymbolAddress((void**)&al,  g_al);
    cudaGetSymbolAddress((void**)&wqh, g_wqh);
    cudaGetSymbolAddress((void**)&wql, g_wql);
    cudaGetSymbolAddress((void**)&woh, g_woh);
    cudaGetSymbolAddress((void**)&wol, g_wol);

    const int attn_smem = 6 * 64 * STR_ * (int)sizeof(__nv_bfloat16);   // 55296
    cudaFuncSetAttribute(gemm_bf16s_kernel<1>,
                         cudaFuncAttributeMaxDynamicSharedMemorySize, GEMM_SMEM);
    cudaFuncSetAttribute(gemm_bf16s_kernel<0>,
                         cudaFuncAttributeMaxDynamicSharedMemorySize, GEMM_SMEM);
    cudaFuncSetAttribute(attn_tc_kernel,
                         cudaFuncAttributeMaxDynamicSharedMemorySize, attn_smem);

    // 0) split fp32 inputs -> hi/lo bf16
    split_kernel<<<(M_ROWS * D_ / 4 + 255) / 256, 256>>>(x, ah, al, M_ROWS * D_ / 4);
    split_kernel<<<(N_QKV * D_ / 4 + 255) / 256, 256>>>(qkv_w, wqh, wql, N_QKV * D_ / 4);
    split_kernel<<<(D_ * D_ / 4 + 255) / 256, 256>>>(out_w, woh, wol, D_ * D_ / 4);

    // 1) QKV projection + bias + q-scale + guard-clamp -> split bf16 QKV
    {
        dim3 grid(N_QKV / 256, M_ROWS / 128);   // 12 x 32
        gemm_bf16s_kernel<1><<<grid, 256, GEMM_SMEM>>>(
            ah, al, wqh, wql, qkv_b, nullptr, qkvh, qkvl, M_ROWS, N_QKV, D_,
            akmin, akmax, avmin, avmax);
    }

    // 2) Tensor-core flash attention (split-bf16 out into ah/al)
    {
        dim3 grid(S_ / 64, H_, B_);
        attn_tc_kernel<<<grid, 128, attn_smem>>>(qkvh, qkvl, ah, al);
    }

    // 3) Output projection (fp32 result)
    {
        dim3 grid(D_ / 256, M_ROWS / 128);      // 4 x 32
        gemm_bf16s_kernel<0><<<grid, 256, GEMM_SMEM>>>(
            ah, al, woh, wol, out_b, out, nullptr, nullptr, M_ROWS, D_, D_,
            nullptr, nullptr, nullptr, nullptr);
    }
}

// round 11
// speedup vs baseline: 1.0907x; 1.0907x over previous
#include <cuda_runtime.h>
#include <cuda_bf16.h>
#include <cstdint>

#define B_   2
#define S_   2048
#define D_   1024
#define H_   16
#define DK_  64
#define EPS_ 0.1f
#define M_ROWS (B_ * S_)          // 4096
#define N_QKV  (3 * D_)           // 3072

// Scratch (allocation-free requirement -> __device__ globals)
__device__ __nv_bfloat16 g_qkvh[M_ROWS * N_QKV];
__device__ __nv_bfloat16 g_qkvl[M_ROWS * N_QKV];
__device__ __nv_bfloat16 g_ah[M_ROWS * D_];
__device__ __nv_bfloat16 g_al[M_ROWS * D_];
__device__ __nv_bfloat16 g_wqh[N_QKV * D_];
__device__ __nv_bfloat16 g_wql[N_QKV * D_];
__device__ __nv_bfloat16 g_woh[D_ * D_];
__device__ __nv_bfloat16 g_wol[D_ * D_];

// ---------------------------------------------------------------------------
// helpers
// ---------------------------------------------------------------------------
__device__ __forceinline__ uint32_t smem_u32(const void* p) {
    return (uint32_t)__cvta_generic_to_shared(p);
}
__device__ __forceinline__ void ldsm_x4(uint32_t& r0, uint32_t& r1, uint32_t& r2,
                                        uint32_t& r3, uint32_t addr) {
    asm volatile("ldmatrix.sync.aligned.m8n8.x4.shared.b16 {%0,%1,%2,%3}, [%4];"
                 : "=r"(r0), "=r"(r1), "=r"(r2), "=r"(r3) : "r"(addr));
}
__device__ __forceinline__ void ldsm_x2(uint32_t& r0, uint32_t& r1, uint32_t addr) {
    asm volatile("ldmatrix.sync.aligned.m8n8.x2.shared.b16 {%0,%1}, [%2];"
                 : "=r"(r0), "=r"(r1) : "r"(addr));
}
__device__ __forceinline__ void ldsm_x2_t(uint32_t& r0, uint32_t& r1, uint32_t addr) {
    asm volatile("ldmatrix.sync.aligned.m8n8.x2.trans.shared.b16 {%0,%1}, [%2];"
                 : "=r"(r0), "=r"(r1) : "r"(addr));
}
__device__ __forceinline__ void mma16816(float c[4], const uint32_t a[4],
                                         const uint32_t b[2]) {
    asm volatile(
        "mma.sync.aligned.m16n8k16.row.col.f32.bf16.bf16.f32 "
        "{%0,%1,%2,%3}, {%4,%5,%6,%7}, {%8,%9}, {%0,%1,%2,%3};"
        : "+f"(c[0]), "+f"(c[1]), "+f"(c[2]), "+f"(c[3])
        : "r"(a[0]), "r"(a[1]), "r"(a[2]), "r"(a[3]), "r"(b[0]), "r"(b[1]));
}
__device__ __forceinline__ uint32_t pack_hi2(float x, float y) {
    __nv_bfloat162 t = __floats2bfloat162_rn(x, y);
    return *(uint32_t*)&t;
}
__device__ __forceinline__ uint32_t pack_lo2(float x, float y) {
    float hx = __bfloat162float(__float2bfloat16(x));
    float hy = __bfloat162float(__float2bfloat16(y));
    __nv_bfloat162 t = __floats2bfloat162_rn(x - hx, y - hy);
    return *(uint32_t*)&t;
}
__device__ __forceinline__ void cpasync16(uint32_t saddr, const void* g) {
    asm volatile("cp.async.ca.shared.global [%0], [%1], 16;" :: "r"(saddr), "l"(g));
}
__device__ __forceinline__ void cpcommit() {
    asm volatile("cp.async.commit_group;");
}
template <int N>
__device__ __forceinline__ void cpwait() {
    asm volatile("cp.async.wait_group %0;" :: "n"(N));
}

// ---------------------------------------------------------------------------
// fp32 -> (hi,lo) bf16 split
// ---------------------------------------------------------------------------
__global__ void split_kernel(const float* __restrict__ in,
                             __nv_bfloat16* __restrict__ hi,
                             __nv_bfloat16* __restrict__ lo, int n4) {
    int i = blockIdx.x * blockDim.x + threadIdx.x;
    if (i >= n4) return;
    float4 f = ((const float4*)in)[i];
    uint2 hh, ll;
    hh.x = pack_hi2(f.x, f.y); hh.y = pack_hi2(f.z, f.w);
    ll.x = pack_lo2(f.x, f.y); ll.y = pack_lo2(f.z, f.w);
    ((uint2*)hi)[i] = hh;
    ((uint2*)lo)[i] = ll;
}

// ---------------------------------------------------------------------------
// guard clamp
// ---------------------------------------------------------------------------
__device__ __forceinline__ float guard_clamp(
    float v, int m, int n,
    const float* __restrict__ akmin, const float* __restrict__ akmax,
    const float* __restrict__ avmin, const float* __restrict__ avmax) {
    const int c = n >> 10;
    const int b  = m >> 11;
    const int h  = (n & 1023) >> 6;
    const int ch = n & 63;
    const int ai = ((b << 4) + h) * 64 + ch;
    const float amin = (c == 1) ? akmin[ai] : avmin[ai];
    const float amax = (c == 1) ? akmax[ai] : avmax[ai];
    float lo = fmaxf(v - EPS_, amin);
    float hi = fminf(v + EPS_, amax);
    lo = fminf(lo, hi);
    return fmaxf(lo, fminf(v, hi));
}

// ---------------------------------------------------------------------------
// Split-bf16 tensor-core GEMM:  C[M,N] = A[M,K] @ B[N,K]^T + bias
// Block tile 128x128, 4 warps (2 M x 2 N), warp tile 64x64.
// BK=16, 4-stage cp.async ring (3 in flight), ONE sync per k-step.
// Stage layout (BYTES): Ah@0 | Al@6144 | Bh@12288 | Bl@18432; stage 24576 B.
// 4 stages = 98304 B smem -> 2 CTAs/SM.
// MODE 1: QKV epilogue (q-scale / kv-clamp, split-bf16 out).  MODE 0: fp32 out.
// ---------------------------------------------------------------------------
#define GSTG    24576            // bytes per stage
#define OFF_AL  6144             // bytes
#define OFF_BH  12288            // bytes
#define OFF_BL  18432            // bytes
#define GEMM_SMEM (4 * GSTG)     // 98304 bytes

template <int MODE>
__global__ __launch_bounds__(128) void gemm_bf16s_kernel(
    const __nv_bfloat16* __restrict__ Ah, const __nv_bfloat16* __restrict__ Al,
    const __nv_bfloat16* __restrict__ Bh, const __nv_bfloat16* __restrict__ Bl,
    const float* __restrict__ bias,
    float* __restrict__ C,
    __nv_bfloat16* __restrict__ Ch, __nv_bfloat16* __restrict__ Cl,
    int M, int N, int K,
    const float* __restrict__ akmin, const float* __restrict__ akmax,
    const float* __restrict__ avmin, const float* __restrict__ avmax)
{
    extern __shared__ __nv_bfloat16 smem[];

    const int tid  = threadIdx.x;
    const int wid  = tid >> 5;
    const int lane = tid & 31;
    const int warp_m = (wid & 1) * 64;
    const int warp_n = (wid >> 1) * 64;
    const int bm = blockIdx.y * 128;
    const int bn = blockIdx.x * 128;

    const int KS = K >> 4;     // 64

    const uint32_t sb0 = smem_u32(smem);

    auto load_stage = [&](int ks, int buf) {
        const uint32_t sb = sb0 + buf * GSTG;
        const int k0 = ks * 16;
#pragma unroll
        for (int i = 0; i < 2; i++) {
            const int chk = tid + i * 128;          // 0..255
            const int r = chk >> 1, c = (chk & 1) * 8;
            const uint32_t sa = sb + (r * 24 + c) * 2;
            const size_t goA = (size_t)(bm + r) * K + k0 + c;
            cpasync16(sa,          Ah + goA);
            cpasync16(sa + OFF_AL, Al + goA);
            const size_t goB = (size_t)(bn + r) * K + k0 + c;
            cpasync16(sa + OFF_BH, Bh + goB);
            cpasync16(sa + OFF_BL, Bl + goB);
        }
        cpcommit();
    };

    float c[4][8][4];
#pragma unroll
    for (int mt = 0; mt < 4; mt++)
#pragma unroll
        for (int nt = 0; nt < 8; nt++)
#pragma unroll
            for (int e = 0; e < 4; e++) c[mt][nt][e] = 0.0f;

    load_stage(0, 0);
    load_stage(1, 1);
    load_stage(2, 2);

    // fragment lane mappings
    const int ar = lane & 15, ac = (lane >> 4) << 3;        // A x4
    const int bprow = (lane & 7) + ((lane >> 4) << 3);      // B x4 row-in-pair
    const int bpcol = ((lane >> 3) & 1) << 3;               // B x4 k-col

    for (int ks = 0; ks < KS; ks++) {
        const int buf = ks & 3;
        cpwait<2>();
        __syncthreads();
        const uint32_t sb = sb0 + buf * GSTG;

        // B fragments: 4 x4-loads cover 8 n-groups (hi and lo)
        uint32_t bfh[8][2], bfl[8][2];
#pragma unroll
        for (int p = 0; p < 4; p++) {
            const uint32_t off = ((warp_n + p * 16 + bprow) * 24 + bpcol) * 2;
            ldsm_x4(bfh[2 * p][0], bfh[2 * p][1], bfh[2 * p + 1][0], bfh[2 * p + 1][1],
                    sb + OFF_BH + off);
            ldsm_x4(bfl[2 * p][0], bfl[2 * p][1], bfl[2 * p + 1][0], bfl[2 * p + 1][1],
                    sb + OFF_BL + off);
        }
#pragma unroll
        for (int mt = 0; mt < 4; mt++) {
            uint32_t afh[4], afl[4];
            const uint32_t aoff = ((warp_m + mt * 16 + ar) * 24 + ac) * 2;
            ldsm_x4(afh[0], afh[1], afh[2], afh[3], sb + aoff);
            ldsm_x4(afl[0], afl[1], afl[2], afl[3], sb + OFF_AL + aoff);
#pragma unroll
            for (int nt = 0; nt < 8; nt++) {
                mma16816(c[mt][nt], afh, bfh[nt]);
                mma16816(c[mt][nt], afh, bfl[nt]);
                mma16816(c[mt][nt], afl, bfh[nt]);
            }
        }
        // safe without a second barrier: the load targets buf (ks-1)&3, whose
        // reads completed before this iteration's sync in every warp
        if (ks + 3 < KS) load_stage(ks + 3, (ks + 3) & 3);
        else cpcommit();   // keep commit-count advancing for the tail
    }

    // Epilogue
    const int g = lane >> 2, t = lane & 3;
#pragma unroll
    for (int mt = 0; mt < 4; mt++) {
#pragma unroll
        for (int nt = 0; nt < 8; nt++) {
            const int n0 = bn + warp_n + nt * 8 + t * 2;
            const float b0 = bias[n0], b1 = bias[n0 + 1];
#pragma unroll
            for (int half = 0; half < 2; half++) {
                const int m = bm + warp_m + mt * 16 + g + half * 8;
                float v0 = c[mt][nt][half * 2 + 0] + b0;
                float v1 = c[mt][nt][half * 2 + 1] + b1;
                if (MODE == 1) {
                    if ((n0 >> 10) == 0) { v0 *= 0.125f; v1 *= 0.125f; }
                    else {
                        v0 = guard_clamp(v0, m, n0,     akmin, akmax, avmin, avmax);
                        v1 = guard_clamp(v1, m, n0 + 1, akmin, akmax, avmin, avmax);
                    }
                    *(uint32_t*)&Ch[(size_t)m * N + n0] = pack_hi2(v0, v1);
                    *(uint32_t*)&Cl[(size_t)m * N + n0] = pack_lo2(v0, v1);
                } else {
                    *(float2*)&C[(size_t)m * N + n0] = make_float2(v0, v1);
                }
            }
        }
    }
}

// ---------------------------------------------------------------------------
// Tensor-core flash attention over pre-split bf16 QKV (round-5, unchanged)
// ---------------------------------------------------------------------------
#define STR_ 72

__global__ __launch_bounds__(128) void attn_tc_kernel(
    const __nv_bfloat16* __restrict__ qkvh,
    const __nv_bfloat16* __restrict__ qkvl,
    __nv_bfloat16* __restrict__ oh, __nv_bfloat16* __restrict__ ol)
{
    extern __shared__ __nv_bfloat16 sb[];
    __nv_bfloat16* sQh = sb;
    __nv_bfloat16* sQl = sQh + 64 * STR_;
    __nv_bfloat16* sKh = sQl + 64 * STR_;
    __nv_bfloat16* sKl = sKh + 64 * STR_;
    __nv_bfloat16* sVh = sKl + 64 * STR_;
    __nv_bfloat16* sVl = sVh + 64 * STR_;

    const int qt = blockIdx.x, h = blockIdx.y, b = blockIdx.z;
    const int tid = threadIdx.x, w = tid >> 5, lane = tid & 31;
    const int g = lane >> 2, t = lane & 3;

#pragma unroll
    for (int it = 0; it < 4; it++) {
        const int idx = tid + it * 128;
        const int r = idx >> 3, c8 = (idx & 7) << 3;
        const size_t gb = ((size_t)(b * S_ + qt * 64 + r) * 3) * 1024 + h * 64 + c8;
        *(uint4*)&sQh[r * STR_ + c8] = *(const uint4*)(qkvh + gb);
        *(uint4*)&sQl[r * STR_ + c8] = *(const uint4*)(qkvl + gb);
    }
    __syncthreads();

    uint32_t aqh[4][4], aql[4][4];
    const int ar = lane & 15, ac8 = (lane >> 4) << 3;
#pragma unroll
    for (int k = 0; k < 4; k++) {
        const int roff = (w * 16 + ar) * STR_ + ac8 + k * 16;
        ldsm_x4(aqh[k][0], aqh[k][1], aqh[k][2], aqh[k][3], smem_u32(&sQh[roff]));
        ldsm_x4(aql[k][0], aql[k][1], aql[k][2], aql[k][3], smem_u32(&sQl[roff]));
    }

    float o[8][4];
#pragma unroll
    for (int dt = 0; dt < 8; dt++)
#pragma unroll
        for (int e = 0; e < 4; e++) o[dt][e] = 0.0f;
    float m0 = -1e30f, m1 = -1e30f, l0 = 0.0f, l1 = 0.0f;

    const int kr = lane & 7, kc = ((lane >> 3) & 1) << 3;
    const int vr = lane & 15;

    for (int kt = 0; kt < S_ / 64; kt++) {
        __syncthreads();
#pragma unroll
        for (int it = 0; it < 4; it++) {
            const int idx = tid + it * 128;
            const int r = idx >> 3, c8 = (idx & 7) << 3;
            const size_t gb =
                ((size_t)(b * S_ + kt * 64 + r) * 3) * 1024 + h * 64 + c8;
            *(uint4*)&sKh[r * STR_ + c8] = *(const uint4*)(qkvh + gb + 1024);
            *(uint4*)&sKl[r * STR_ + c8] = *(const uint4*)(qkvl + gb + 1024);
            *(uint4*)&sVh[r * STR_ + c8] = *(const uint4*)(qkvh + gb + 2048);
            *(uint4*)&sVl[r * STR_ + c8] = *(const uint4*)(qkvl + gb + 2048);
        }
        __syncthreads();

        float sc[8][4];
#pragma unroll
        for (int nt = 0; nt < 8; nt++)
#pragma unroll
            for (int e = 0; e < 4; e++) sc[nt][e] = 0.0f;
#pragma unroll
        for (int k = 0; k < 4; k++) {
#pragma unroll
            for (int nt = 0; nt < 8; nt++) {
                uint32_t bh[2], bl[2];
                const int boff = (nt * 8 + kr) * STR_ + kc + k * 16;
                ldsm_x2(bh[0], bh[1], smem_u32(&sKh[boff]));
                ldsm_x2(bl[0], bl[1], smem_u32(&sKl[boff]));
                mma16816(sc[nt], aqh[k], bh);
                mma16816(sc[nt], aqh[k], bl);
                mma16816(sc[nt], aql[k], bh);
            }
        }

        float mx0 = -1e30f, mx1 = -1e30f;
#pragma unroll
        for (int nt = 0; nt < 8; nt++) {
            mx0 = fmaxf(mx0, fmaxf(sc[nt][0], sc[nt][1]));
            mx1 = fmaxf(mx1, fmaxf(sc[nt][2], sc[nt][3]));
        }
        mx0 = fmaxf(mx0, __shfl_xor_sync(0xffffffffu, mx0, 1));
        mx0 = fmaxf(mx0, __shfl_xor_sync(0xffffffffu, mx0, 2));
        mx1 = fmaxf(mx1, __shfl_xor_sync(0xffffffffu, mx1, 1));
        mx1 = fmaxf(mx1, __shfl_xor_sync(0xffffffffu, mx1, 2));
        const float mn0 = fmaxf(m0, mx0), mn1 = fmaxf(m1, mx1);
        const float c0 = __expf(m0 - mn0), c1 = __expf(m1 - mn1);
        float rs0 = 0.0f, rs1 = 0.0f;
#pragma unroll
        for (int nt = 0; nt < 8; nt++) {
            sc[nt][0] = __expf(sc[nt][0] - mn0);
            sc[nt][1] = __expf(sc[nt][1] - mn0);
            sc[nt][2] = __expf(sc[nt][2] - mn1);
            sc[nt][3] = __expf(sc[nt][3] - mn1);
            rs0 += sc[nt][0] + sc[nt][1];
            rs1 += sc[nt][2] + sc[nt][3];
        }
        rs0 += __shfl_xor_sync(0xffffffffu, rs0, 1);
        rs0 += __shfl_xor_sync(0xffffffffu, rs0, 2);
        rs1 += __shfl_xor_sync(0xffffffffu, rs1, 1);
        rs1 += __shfl_xor_sync(0xffffffffu, rs1, 2);
        l0 = l0 * c0 + rs0;
        l1 = l1 * c1 + rs1;
        m0 = mn0; m1 = mn1;
#pragma unroll
        for (int dt = 0; dt < 8; dt++) {
            o[dt][0] *= c0; o[dt][1] *= c0;
            o[dt][2] *= c1; o[dt][3] *= c1;
        }

#pragma unroll
        for (int kq = 0; kq < 4; kq++) {
            uint32_t ph[4], pl[4];
            ph[0] = pack_hi2(sc[2 * kq][0], sc[2 * kq][1]);
            ph[1] = pack_hi2(sc[2 * kq][2], sc[2 * kq][3]);
            ph[2] = pack_hi2(sc[2 * kq + 1][0], sc[2 * kq + 1][1]);
            ph[3] = pack_hi2(sc[2 * kq + 1][2], sc[2 * kq + 1][3]);
            pl[0] = pack_lo2(sc[2 * kq][0], sc[2 * kq][1]);
            pl[1] = pack_lo2(sc[2 * kq][2], sc[2 * kq][3]);
            pl[2] = pack_lo2(sc[2 * kq + 1][0], sc[2 * kq + 1][1]);
            pl[3] = pack_lo2(sc[2 * kq + 1][2], sc[2 * kq + 1][3]);
#pragma unroll
            for (int dt = 0; dt < 8; dt++) {
                uint32_t bvh[2], bvl[2];
                const int voff = (kq * 16 + vr) * STR_ + dt * 8;
                ldsm_x2_t(bvh[0], bvh[1], smem_u32(&sVh[voff]));
                ldsm_x2_t(bvl[0], bvl[1], smem_u32(&sVl[voff]));
                mma16816(o[dt], ph, bvh);
                mma16816(o[dt], ph, bvl);
                mma16816(o[dt], pl, bvh);
            }
        }
    }

    const float inv0 = 1.0f / l0, inv1 = 1.0f / l1;
    const int r0 = qt * 64 + w * 16 + g;
    const int r1 = r0 + 8;
#pragma unroll
    for (int dt = 0; dt < 8; dt++) {
        const int d0 = h * 64 + dt * 8 + t * 2;
        const float x0 = o[dt][0] * inv0, x1 = o[dt][1] * inv0;
        const float y0 = o[dt][2] * inv1, y1 = o[dt][3] * inv1;
        const size_t p0 = (size_t)(b * S_ + r0) * 1024 + d0;
        const size_t p1 = (size_t)(b * S_ + r1) * 1024 + d0;
        *(uint32_t*)&oh[p0] = pack_hi2(x0, x1);
        *(uint32_t*)&ol[p0] = pack_lo2(x0, x1);
        *(uint32_t*)&oh[p1] = pack_hi2(y0, y1);
        *(uint32_t*)&ol[p1] = pack_lo2(y0, y1);
    }
}

// ---------------------------------------------------------------------------
extern "C" void kernel_launch(void* const* d_in, const int* in_sizes, int n_in,
                              void* d_out, int out_size)
{
    const float* x      = (const float*)d_in[0];
    const float* qkv_w  = (const float*)d_in[1];
    const float* qkv_b  = (const float*)d_in[2];
    const float* out_w  = (const float*)d_in[3];
    const float* out_b  = (const float*)d_in[4];
    const float* akmin  = (const float*)d_in[5];
    const float* akmax  = (const float*)d_in[6];
    const float* avmin  = (const float*)d_in[7];
    const float* avmax  = (const float*)d_in[8];
    float* out = (float*)d_out;

    __nv_bfloat16 *qkvh, *qkvl, *ah, *al, *wqh, *wql, *woh, *wol;
    cudaGetSymbolAddress((void**)&qkvh, g_qkvh);
    cudaGetSymbolAddress((void**)&qkvl, g_qkvl);
    cudaGetSymbolAddress((void**)&ah,  g_ah);
    cudaGetSymbolAddress((void**)&al,  g_al);
    cudaGetSymbolAddress((void**)&wqh, g_wqh);
    cudaGetSymbolAddress((void**)&wql, g_wql);
    cudaGetSymbolAddress((void**)&woh, g_woh);
    cudaGetSymbolAddress((void**)&wol, g_wol);

    const int attn_smem = 6 * 64 * STR_ * (int)sizeof(__nv_bfloat16);   // 55296
    cudaFuncSetAttribute(gemm_bf16s_kernel<1>,
                         cudaFuncAttributeMaxDynamicSharedMemorySize, GEMM_SMEM);
    cudaFuncSetAttribute(gemm_bf16s_kernel<0>,
                         cudaFuncAttributeMaxDynamicSharedMemorySize, GEMM_SMEM);
    cudaFuncSetAttribute(attn_tc_kernel,
                         cudaFuncAttributeMaxDynamicSharedMemorySize, attn_smem);

    // 0) split fp32 inputs -> hi/lo bf16
    split_kernel<<<(M_ROWS * D_ / 4 + 255) / 256, 256>>>(x, ah, al, M_ROWS * D_ / 4);
    split_kernel<<<(N_QKV * D_ / 4 + 255) / 256, 256>>>(qkv_w, wqh, wql, N_QKV * D_ / 4);
    split_kernel<<<(D_ * D_ / 4 + 255) / 256, 256>>>(out_w, woh, wol, D_ * D_ / 4);

    // 1) QKV projection + bias + q-scale + guard-clamp -> split bf16 QKV
    {
        dim3 grid(N_QKV / 128, M_ROWS / 128);   // 24 x 32
        gemm_bf16s_kernel<1><<<grid, 128, GEMM_SMEM>>>(
            ah, al, wqh, wql, qkv_b, nullptr, qkvh, qkvl, M_ROWS, N_QKV, D_,
            akmin, akmax, avmin, avmax);
    }

    // 2) Tensor-core flash attention (split-bf16 out into ah/al)
    {
        dim3 grid(S_ / 64, H_, B_);
        attn_tc_kernel<<<grid, 128, attn_smem>>>(qkvh, qkvl, ah, al);
    }

    // 3) Output projection (fp32 result)
    {
        dim3 grid(D_ / 128, M_ROWS / 128);      // 8 x 32
        gemm_bf16s_kernel<0><<<grid, 128, GEMM_SMEM>>>(
            ah, al, woh, wol, out_b, out, nullptr, nullptr, M_ROWS, D_, D_,
            nullptr, nullptr, nullptr, nullptr);
    }
}